// round 1
// baseline (speedup 1.0000x reference)
#include <cuda_runtime.h>
#include <cuda_bf16.h>

// ---------------- problem constants ----------------
#define NC 96          // B*C = 32*3
#define S0 510
#define S1 258         // (510+7)/2
#define S2 132         // (258+7)/2

// ---------------- static scratch (no cudaMalloc allowed) ----------------
__device__ float g_rlo1[NC * S0 * S1];   // 50.5 MB  (also reused by idwt level-1 col stage)
__device__ float g_rhi1[NC * S0 * S1];   // 50.5 MB
__device__ float g_a1 [NC * S1 * S1];    // 25.6 MB  (a1, later overwritten by a1r)
__device__ float g_h1 [NC * S1 * S1];
__device__ float g_v1 [NC * S1 * S1];
__device__ float g_d1 [NC * S1 * S1];
__device__ float g_rlo2[NC * S1 * S2];   // 13.1 MB  (also reused by idwt level-2 col stage)
__device__ float g_rhi2[NC * S1 * S2];
__device__ float g_a2 [NC * S2 * S2];    // 6.7 MB
__device__ float g_h2 [NC * S2 * S2];
__device__ float g_v2 [NC * S2 * S2];
__device__ float g_d2 [NC * S2 * S2];
__device__ float g_max[6 * NC];          // abs-max per (band, nc); bands: h1,v1,d1,h2,v2,d2

// db4: CLO = rec_lo, CHI = rec_hi. Analysis correlation starting at x[2k-6] uses
// exactly these arrays (dec_lo[7-t]=rec_lo[t], dec_hi[7-t]=rec_hi[t]).
__constant__ float CLO[8] = {
     0.23037781330885523f,  0.7148465705525415f,   0.6308807679295904f,
    -0.02798376941698385f, -0.18703481171888114f,  0.030841381835986965f,
     0.032883011666982945f,-0.010597401784997278f };
__constant__ float CHI[8] = {
    -0.010597401784997278f,-0.032883011666982945f, 0.030841381835986965f,
     0.18703481171888114f, -0.02798376941698385f, -0.6308807679295904f,
     0.7148465705525415f,  -0.23037781330885523f };

__device__ __forceinline__ int reflect(int idx, int S) {
    // half-sample symmetric; single reflection suffices (|overhang| <= 6 < S)
    if (idx < 0)  return -1 - idx;
    if (idx >= S) return 2 * S - 1 - idx;
    return idx;
}

// ---------------- analysis: rows ----------------
__global__ void dwt_row(const float* __restrict__ x, float* __restrict__ lo,
                        float* __restrict__ hi, int S, int So) {
    int k   = blockIdx.x * blockDim.x + threadIdx.x;
    int row = blockIdx.y;
    if (k >= So) return;
    const float* xr = x + (size_t)row * S;
    int base = 2 * k - 6;
    float al = 0.f, ah = 0.f;
#pragma unroll
    for (int t = 0; t < 8; t++) {
        float v = xr[reflect(base + t, S)];
        al = fmaf(v, CLO[t], al);
        ah = fmaf(v, CHI[t], ah);
    }
    lo[(size_t)row * So + k] = al;
    hi[(size_t)row * So + k] = ah;
}

// ---------------- analysis: columns ----------------
__global__ void dwt_col(const float* __restrict__ x, float* __restrict__ lo,
                        float* __restrict__ hi, int H, int W, int Ho) {
    int w  = blockIdx.x * blockDim.x + threadIdx.x;
    int k  = blockIdx.y;
    int nc = blockIdx.z;
    if (w >= W) return;
    const float* xp = x + (size_t)nc * H * W;
    int base = 2 * k - 6;
    float al = 0.f, ah = 0.f;
#pragma unroll
    for (int t = 0; t < 8; t++) {
        float v = xp[(size_t)reflect(base + t, H) * W + w];
        al = fmaf(v, CLO[t], al);
        ah = fmaf(v, CHI[t], ah);
    }
    lo[((size_t)nc * Ho + k) * W + w] = al;
    hi[((size_t)nc * Ho + k) * W + w] = ah;
}

// ---------------- abs-max over each detail band ----------------
__global__ void init_max() {
    int i = blockIdx.x * blockDim.x + threadIdx.x;
    if (i < 6 * NC) g_max[i] = 0.f;
}

__global__ void absmax6(const float* __restrict__ h1, const float* __restrict__ v1,
                        const float* __restrict__ d1, const float* __restrict__ h2,
                        const float* __restrict__ v2, const float* __restrict__ d2) {
    int nc = blockIdx.x, band = blockIdx.y, split = blockIdx.z;
    const float* p; int n;
    switch (band) {
        case 0: p = h1; n = S1 * S1; break;
        case 1: p = v1; n = S1 * S1; break;
        case 2: p = d1; n = S1 * S1; break;
        case 3: p = h2; n = S2 * S2; break;
        case 4: p = v2; n = S2 * S2; break;
        default: p = d2; n = S2 * S2; break;
    }
    p += (size_t)nc * n;
    int per   = (n + gridDim.z - 1) / gridDim.z;
    int start = split * per;
    int end   = min(n, start + per);
    float m = 0.f;
    for (int i = start + threadIdx.x; i < end; i += blockDim.x)
        m = fmaxf(m, fabsf(p[i]));
    __shared__ float sm[256];
    sm[threadIdx.x] = m;
    __syncthreads();
    for (int s = 128; s > 0; s >>= 1) {
        if (threadIdx.x < s) sm[threadIdx.x] = fmaxf(sm[threadIdx.x], sm[threadIdx.x + s]);
        __syncthreads();
    }
    if (threadIdx.x == 0)
        atomicMax((int*)&g_max[band * NC + nc], __float_as_int(sm[0]));
    // abs values are non-negative floats -> int bit-pattern ordering is monotone
}

// ---------------- synthesis: columns (with fused soft-enhance on loads) ----------------
__global__ void idwt_col(const float* __restrict__ A, const float* __restrict__ D,
                         float* __restrict__ out, int Hc, int W, int Ho,
                         int enhA, int idxA, int enhD, int idxD) {
    int w  = blockIdx.x * blockDim.x + threadIdx.x;
    int m  = blockIdx.y;
    int nc = blockIdx.z;
    if (w >= W) return;
    const float* a = A + (size_t)nc * Hc * W;
    const float* d = D + (size_t)nc * Hc * W;
    float tA = enhA ? 0.3f * g_max[idxA * NC + nc] : 0.f;
    float tD = enhD ? 0.3f * g_max[idxD * NC + nc] : 0.f;
    int q0    = m >> 1;
    int fbase = (m & 1) ? 7 : 6;
    float acc = 0.f;
#pragma unroll
    for (int i = 0; i < 4; i++) {
        int f = fbase - 2 * i;
        float av = a[(size_t)(q0 + i) * W + w];
        float dv = d[(size_t)(q0 + i) * W + w];
        if (enhA) av = copysignf(fmaxf(1.5f * fabsf(av) - tA, 0.f), av);
        if (enhD) dv = copysignf(fmaxf(1.5f * fabsf(dv) - tD, 0.f), dv);
        acc = fmaf(av, CLO[f], fmaf(dv, CHI[f], acc));
    }
    out[((size_t)nc * Ho + m) * W + w] = acc;
}

// ---------------- synthesis: rows ----------------
__global__ void idwt_row(const float* __restrict__ lo, const float* __restrict__ hi,
                         float* __restrict__ out, int n, int Wout) {
    int m   = blockIdx.x * blockDim.x + threadIdx.x;
    int row = blockIdx.y;
    if (m >= Wout) return;
    const float* lr = lo + (size_t)row * n;
    const float* hr = hi + (size_t)row * n;
    int q0    = m >> 1;
    int fbase = (m & 1) ? 7 : 6;
    float acc = 0.f;
#pragma unroll
    for (int i = 0; i < 4; i++) {
        int f = fbase - 2 * i;
        acc = fmaf(lr[q0 + i], CLO[f], fmaf(hr[q0 + i], CHI[f], acc));
    }
    out[(size_t)row * Wout + m] = acc;
}

// ---------------- host ----------------
static inline unsigned cdiv(unsigned a, unsigned b) { return (a + b - 1) / b; }

extern "C" void kernel_launch(void* const* d_in, const int* in_sizes, int n_in,
                              void* d_out, int out_size) {
    (void)in_sizes; (void)n_in; (void)out_size;
    const float* x = (const float*)d_in[0];
    float* out = (float*)d_out;

    float *rlo1, *rhi1, *a1, *h1, *v1, *d1, *rlo2, *rhi2, *a2, *h2, *v2, *d2;
    cudaGetSymbolAddress((void**)&rlo1, g_rlo1);
    cudaGetSymbolAddress((void**)&rhi1, g_rhi1);
    cudaGetSymbolAddress((void**)&a1,  g_a1);
    cudaGetSymbolAddress((void**)&h1,  g_h1);
    cudaGetSymbolAddress((void**)&v1,  g_v1);
    cudaGetSymbolAddress((void**)&d1,  g_d1);
    cudaGetSymbolAddress((void**)&rlo2, g_rlo2);
    cudaGetSymbolAddress((void**)&rhi2, g_rhi2);
    cudaGetSymbolAddress((void**)&a2,  g_a2);
    cudaGetSymbolAddress((void**)&h2,  g_h2);
    cudaGetSymbolAddress((void**)&v2,  g_v2);
    cudaGetSymbolAddress((void**)&d2,  g_d2);

    const int TB = 128;

    // Level-1 analysis
    dwt_row<<<dim3(cdiv(S1, TB), NC * S0), TB>>>(x, rlo1, rhi1, S0, S1);
    dwt_col<<<dim3(cdiv(S1, TB), S1, NC), TB>>>(rlo1, a1, h1, S0, S1, S1);
    dwt_col<<<dim3(cdiv(S1, TB), S1, NC), TB>>>(rhi1, v1, d1, S0, S1, S1);

    // Level-2 analysis (on a1)
    dwt_row<<<dim3(cdiv(S2, TB), NC * S1), TB>>>(a1, rlo2, rhi2, S1, S2);
    dwt_col<<<dim3(cdiv(S2, TB), S2, NC), TB>>>(rlo2, a2, h2, S1, S2, S2);
    dwt_col<<<dim3(cdiv(S2, TB), S2, NC), TB>>>(rhi2, v2, d2, S1, S2, S2);

    // Per-band abs-max (raw values; threshold = 0.3*max fused into idwt_col)
    init_max<<<3, 256>>>();
    absmax6<<<dim3(NC, 6, 4), 256>>>(h1, v1, d1, h2, v2, d2);

    // Level-2 synthesis -> a1r (overwrites a1)
    idwt_col<<<dim3(cdiv(S2, TB), S1, NC), TB>>>(a2, h2, rlo2, S2, S2, S1, 0, 0, 1, 3);
    idwt_col<<<dim3(cdiv(S2, TB), S1, NC), TB>>>(v2, d2, rhi2, S2, S2, S1, 1, 4, 1, 5);
    idwt_row<<<dim3(cdiv(S1, TB), NC * S1), TB>>>(rlo2, rhi2, a1, S2, S1);

    // Level-1 synthesis -> output
    idwt_col<<<dim3(cdiv(S1, TB), S0, NC), TB>>>(a1, h1, rlo1, S1, S1, S0, 0, 0, 1, 0);
    idwt_col<<<dim3(cdiv(S1, TB), S0, NC), TB>>>(v1, d1, rhi1, S1, S1, S0, 1, 1, 1, 2);
    idwt_row<<<dim3(cdiv(S0, TB), NC * S0), TB>>>(rlo1, rhi1, out, S1, S0);
}

// round 2
// speedup vs baseline: 2.1990x; 2.1990x over previous
#include <cuda_runtime.h>
#include <cuda_bf16.h>

// ---------------- problem constants ----------------
#define NC 96          // B*C = 32*3
#define S0 510
#define S1 258         // (510+7)/2
#define S2 132         // (258+7)/2

// ---------------- static scratch ----------------
__device__ float g_a1[NC * S1 * S1];   // a1, later overwritten by a1r
__device__ float g_h1[NC * S1 * S1];
__device__ float g_v1[NC * S1 * S1];
__device__ float g_d1[NC * S1 * S1];
__device__ float g_a2[NC * S2 * S2];
__device__ float g_h2[NC * S2 * S2];
__device__ float g_v2[NC * S2 * S2];
__device__ float g_d2[NC * S2 * S2];
__device__ float g_max[6 * NC];        // bands: 0..2 = h1,v1,d1 ; 3..5 = h2,v2,d2

// db4 synthesis filters; analysis correlation starting at x[2k-6] uses the same
// arrays (dec_lo[7-t]=rec_lo[t], dec_hi[7-t]=rec_hi[t]).  Verified in round 1.
__constant__ float CLO[8] = {
     0.23037781330885523f,  0.7148465705525415f,   0.6308807679295904f,
    -0.02798376941698385f, -0.18703481171888114f,  0.030841381835986965f,
     0.032883011666982945f,-0.010597401784997278f };
__constant__ float CHI[8] = {
    -0.010597401784997278f,-0.032883011666982945f, 0.030841381835986965f,
     0.18703481171888114f, -0.02798376941698385f, -0.6308807679295904f,
     0.7148465705525415f,  -0.23037781330885523f };

__device__ __forceinline__ int reflect(int idx, int S) {
    // half-sample symmetric; single reflection suffices (|overhang| < S here)
    if (idx < 0)  return -1 - idx;
    if (idx >= S) return 2 * S - 1 - idx;
    return idx;
}

__device__ __forceinline__ float soft(float x, float t) {
    return copysignf(fmaxf(fabsf(x) * 1.5f - t, 0.f), x);
}

// ---------------- init ----------------
__global__ void init_max() {
    int i = blockIdx.x * blockDim.x + threadIdx.x;
    if (i < 6 * NC) g_max[i] = 0.f;
}

// ---------------- fused 2-D analysis (row pass -> smem -> col pass + absmax) ----
// Output tile: TKH x TKW coefficients per band.  Intermediate: R = 2*TKH+6 rows
// of row-transformed lo/hi in smem.  BB = band base index into g_max.
template<int H, int W, int Hc, int Wc, int BB>
__global__ void fused_dwt2(const float* __restrict__ x,
                           float* __restrict__ aa, float* __restrict__ da,
                           float* __restrict__ ad, float* __restrict__ dd) {
    constexpr int TKH = 16, TKW = 32, R = 2 * TKH + 6;  // 38
    __shared__ float slo[R][TKW];
    __shared__ float shi[R][TKW];
    const int kw0 = blockIdx.x * TKW;
    const int kh0 = blockIdx.y * TKH;
    const int nc  = blockIdx.z;
    const int tid = threadIdx.x;
    const float* xp = x + (size_t)nc * H * W;

    // Phase 1: row DWT for the 38 (reflected) input rows this tile needs.
    for (int idx = tid; idx < R * TKW; idx += 256) {
        int rr = idx / TKW, c = idx % TKW;
        int r = reflect(2 * kh0 - 6 + rr, H);
        const float* xr = xp + (size_t)r * W;
        int base = 2 * (kw0 + c) - 6;
        float al = 0.f, ah = 0.f;
#pragma unroll
        for (int t = 0; t < 8; t++) {
            float v = xr[reflect(base + t, W)];
            al = fmaf(v, CLO[t], al);
            ah = fmaf(v, CHI[t], ah);
        }
        slo[rr][c] = al;
        shi[rr][c] = ah;
    }
    __syncthreads();

    // Phase 2: column DWT from smem; track detail-band abs maxima.
    float m_h = 0.f, m_v = 0.f, m_d = 0.f;
    for (int idx = tid; idx < TKH * TKW; idx += 256) {
        int khl = idx / TKW, c = idx % TKW;
        int kh = kh0 + khl, kw = kw0 + c;
        float va = 0.f, vh = 0.f, vv = 0.f, vd = 0.f;
#pragma unroll
        for (int t = 0; t < 8; t++) {
            float l = slo[2 * khl + t][c];
            float h = shi[2 * khl + t][c];
            va = fmaf(l, CLO[t], va);
            vh = fmaf(l, CHI[t], vh);
            vv = fmaf(h, CLO[t], vv);
            vd = fmaf(h, CHI[t], vd);
        }
        if (kh < Hc && kw < Wc) {
            size_t o = ((size_t)nc * Hc + kh) * Wc + kw;
            aa[o] = va; da[o] = vh; ad[o] = vv; dd[o] = vd;
            m_h = fmaxf(m_h, fabsf(vh));
            m_v = fmaxf(m_v, fabsf(vv));
            m_d = fmaxf(m_d, fabsf(vd));
        }
    }

    // Phase 3: block-reduce the 3 maxima, one atomicMax per band.
#pragma unroll
    for (int o = 16; o > 0; o >>= 1) {
        m_h = fmaxf(m_h, __shfl_xor_sync(0xffffffffu, m_h, o));
        m_v = fmaxf(m_v, __shfl_xor_sync(0xffffffffu, m_v, o));
        m_d = fmaxf(m_d, __shfl_xor_sync(0xffffffffu, m_d, o));
    }
    __shared__ float rmax[8][3];
    int wid = tid >> 5, lane = tid & 31;
    if (lane == 0) { rmax[wid][0] = m_h; rmax[wid][1] = m_v; rmax[wid][2] = m_d; }
    __syncthreads();
    if (tid < 3) {
        float m = rmax[0][tid];
#pragma unroll
        for (int i = 1; i < 8; i++) m = fmaxf(m, rmax[i][tid]);
        atomicMax((int*)&g_max[(BB + tid) * NC + nc], __float_as_int(m));
        // abs values are non-negative floats -> int ordering is monotone
    }
}

// ---------------- fused 2-D synthesis (col pass + soft-enhance -> smem -> row pass)
// Output tile: TM x TW pixels.  Intermediate: TM rows x J columns of
// column-synthesized lo/hi.  A band is never enhanced; Dh/Dv/Dd use
// thresholds 0.3*g_max[BB+0..2].  All coefficient indices are in-bounds
// (verified: q0+3 <= Hc-1 for m < H = 2*Hc-6).
template<int Hc, int Wc, int H, int W, int BB>
__global__ void fused_idwt2(const float* __restrict__ A,  const float* __restrict__ Dh,
                            const float* __restrict__ Dv, const float* __restrict__ Dd,
                            float* __restrict__ out) {
    constexpr int TM = 32, TW = 64, J = TW / 2 + 4;  // 36
    __shared__ float slo[TM][J];
    __shared__ float shi[TM][J];
    const int w0 = blockIdx.x * TW;
    const int m0 = blockIdx.y * TM;
    const int nc = blockIdx.z;
    const int tid = threadIdx.x;
    const float th = 0.3f * g_max[(BB + 0) * NC + nc];
    const float tv = 0.3f * g_max[(BB + 1) * NC + nc];
    const float td = 0.3f * g_max[(BB + 2) * NC + nc];
    const size_t cb = (size_t)nc * Hc * Wc;
    const float* Ap = A  + cb;
    const float* Hp = Dh + cb;
    const float* Vp = Dv + cb;
    const float* Dp = Dd + cb;

    // Phase 1: column IDWT (with fused soft-enhance) into smem.
    for (int idx = tid; idx < TM * J; idx += 256) {
        int ml = idx / J, j = idx % J;
        int m = m0 + ml, wc = w0 / 2 + j;
        if (m < H && wc < Wc) {
            int q0 = m >> 1;
            int fb = (m & 1) ? 7 : 6;
            float lo = 0.f, hi = 0.f;
#pragma unroll
            for (int i = 0; i < 4; i++) {
                int f = fb - 2 * i;
                size_t o = (size_t)(q0 + i) * Wc + wc;
                float av = Ap[o];
                float hv = soft(Hp[o], th);
                float vv = soft(Vp[o], tv);
                float dv = soft(Dp[o], td);
                lo = fmaf(av, CLO[f], fmaf(hv, CHI[f], lo));
                hi = fmaf(vv, CLO[f], fmaf(dv, CHI[f], hi));
            }
            slo[ml][j] = lo;
            shi[ml][j] = hi;
        }
    }
    __syncthreads();

    // Phase 2: row IDWT from smem to output.
    const size_t ob = (size_t)nc * H * W;
    for (int idx = tid; idx < TM * TW; idx += 256) {
        int ml = idx / TW, wl = idx % TW;
        int m = m0 + ml, w = w0 + wl;
        if (m < H && w < W) {
            int jb = (w >> 1) - w0 / 2;
            int fb = (w & 1) ? 7 : 6;
            float acc = 0.f;
#pragma unroll
            for (int i = 0; i < 4; i++) {
                int f = fb - 2 * i;
                acc = fmaf(slo[ml][jb + i], CLO[f], fmaf(shi[ml][jb + i], CHI[f], acc));
            }
            out[ob + (size_t)m * W + w] = acc;
        }
    }
}

// ---------------- host ----------------
static inline unsigned cdiv(unsigned a, unsigned b) { return (a + b - 1) / b; }

extern "C" void kernel_launch(void* const* d_in, const int* in_sizes, int n_in,
                              void* d_out, int out_size) {
    (void)in_sizes; (void)n_in; (void)out_size;
    const float* x = (const float*)d_in[0];
    float* out = (float*)d_out;

    float *a1, *h1, *v1, *d1, *a2, *h2, *v2, *d2;
    cudaGetSymbolAddress((void**)&a1, g_a1);
    cudaGetSymbolAddress((void**)&h1, g_h1);
    cudaGetSymbolAddress((void**)&v1, g_v1);
    cudaGetSymbolAddress((void**)&d1, g_d1);
    cudaGetSymbolAddress((void**)&a2, g_a2);
    cudaGetSymbolAddress((void**)&h2, g_h2);
    cudaGetSymbolAddress((void**)&v2, g_v2);
    cudaGetSymbolAddress((void**)&d2, g_d2);

    init_max<<<3, 256>>>();

    // Level-1 analysis: x -> a1,h1,v1,d1  (+ absmax of h1,v1,d1 -> bands 0..2)
    fused_dwt2<S0, S0, S1, S1, 0><<<dim3(cdiv(S1, 32), cdiv(S1, 16), NC), 256>>>(
        x, a1, h1, v1, d1);

    // Level-2 analysis: a1 -> a2,h2,v2,d2 (+ absmax -> bands 3..5)
    fused_dwt2<S1, S1, S2, S2, 3><<<dim3(cdiv(S2, 32), cdiv(S2, 16), NC), 256>>>(
        a1, a2, h2, v2, d2);

    // Level-2 synthesis: (a2, h2s, v2s, d2s) -> a1r (overwrites a1)
    fused_idwt2<S2, S2, S1, S1, 3><<<dim3(cdiv(S1, 64), cdiv(S1, 32), NC), 256>>>(
        a2, h2, v2, d2, a1);

    // Level-1 synthesis: (a1r, h1s, v1s, d1s) -> out
    fused_idwt2<S1, S1, S0, S0, 0><<<dim3(cdiv(S0, 64), cdiv(S0, 32), NC), 256>>>(
        a1, h1, v1, d1, out);
}

// round 3
// speedup vs baseline: 2.6231x; 1.1929x over previous
#include <cuda_runtime.h>
#include <cuda_bf16.h>

// ---------------- problem constants ----------------
#define NC 96          // B*C = 32*3
#define S0 510
#define S1 258         // (510+7)/2
#define S2 132         // (258+7)/2

// ---------------- static scratch ----------------
__device__ float g_a1[NC * S1 * S1];   // a1, later overwritten by a1r
__device__ float g_h1[NC * S1 * S1];
__device__ float g_v1[NC * S1 * S1];
__device__ float g_d1[NC * S1 * S1];
__device__ float g_a2[NC * S2 * S2];
__device__ float g_h2[NC * S2 * S2];
__device__ float g_v2[NC * S2 * S2];
__device__ float g_d2[NC * S2 * S2];
__device__ float g_max[6 * NC];        // bands: 0..2 = h1,v1,d1 ; 3..5 = h2,v2,d2

// db4 synthesis filters; analysis correlation starting at x[2k-6] uses the same
// arrays (dec_lo[7-t]=rec_lo[t], dec_hi[7-t]=rec_hi[t]).  Verified round 1.
__constant__ float CLO[8] = {
     0.23037781330885523f,  0.7148465705525415f,   0.6308807679295904f,
    -0.02798376941698385f, -0.18703481171888114f,  0.030841381835986965f,
     0.032883011666982945f,-0.010597401784997278f };
__constant__ float CHI[8] = {
    -0.010597401784997278f,-0.032883011666982945f, 0.030841381835986965f,
     0.18703481171888114f, -0.02798376941698385f, -0.6308807679295904f,
     0.7148465705525415f,  -0.23037781330885523f };

__device__ __forceinline__ int reflect(int idx, int S) {
    if (idx < 0)  return -1 - idx;
    if (idx >= S) return 2 * S - 1 - idx;
    return idx;
}

__device__ __forceinline__ float soft(float x, float t) {
    return copysignf(fmaxf(fabsf(x) * 1.5f - t, 0.f), x);
}

__global__ void init_max() {
    int i = blockIdx.x * blockDim.x + threadIdx.x;
    if (i < 6 * NC) g_max[i] = 0.f;
}

// ---------------- fused 2-D analysis ------------------------------------
// Phase 0: stage the raw (reflected) input tile in smem   (each elem once)
// Phase 1: row DWT  smem -> smem
// Phase 2: col DWT  smem -> global (4 bands) + block absmax of detail bands
template<int H, int W, int Hc, int Wc, int BB>
__global__ void fused_dwt2(const float* __restrict__ x,
                           float* __restrict__ aa, float* __restrict__ da,
                           float* __restrict__ ad, float* __restrict__ dd) {
    constexpr int TKH = 16, TKW = 32;
    constexpr int R  = 2 * TKH + 6;        // 38 intermediate rows
    constexpr int CT = 2 * TKW + 6;        // 70 staged input cols
    constexpr int CP = 72;                 // padded width
    __shared__ float sx [R][CP];
    __shared__ float slo[R][TKW];
    __shared__ float shi[R][TKW];

    const int kw0 = blockIdx.x * TKW;
    const int kh0 = blockIdx.y * TKH;
    const int nc  = blockIdx.z;
    const int tid = threadIdx.x;
    const float* xp = x + (size_t)nc * H * W;

    // Phase 0: stage input tile (rows 2*kh0-6 .. +37, cols 2*kw0-6 .. +69, reflected)
    for (int idx = tid; idx < R * CT; idx += 256) {
        int rr = idx / CT, cc = idx % CT;
        int r = reflect(2 * kh0 - 6 + rr, H);
        int c = reflect(2 * kw0 - 6 + cc, W);
        sx[rr][cc] = xp[(size_t)r * W + c];
    }
    __syncthreads();

    // Phase 1: row DWT from smem (output col k = kw0+c reads sx[rr][2c .. 2c+7])
    for (int idx = tid; idx < R * TKW; idx += 256) {
        int rr = idx / TKW, c = idx % TKW;
        float al = 0.f, ah = 0.f;
#pragma unroll
        for (int t = 0; t < 8; t++) {
            float v = sx[rr][2 * c + t];
            al = fmaf(v, CLO[t], al);
            ah = fmaf(v, CHI[t], ah);
        }
        slo[rr][c] = al;
        shi[rr][c] = ah;
    }
    __syncthreads();

    // Phase 2: column DWT + detail-band abs maxima.
    float m_h = 0.f, m_v = 0.f, m_d = 0.f;
    for (int idx = tid; idx < TKH * TKW; idx += 256) {
        int khl = idx / TKW, c = idx % TKW;
        int kh = kh0 + khl, kw = kw0 + c;
        float va = 0.f, vh = 0.f, vv = 0.f, vd = 0.f;
#pragma unroll
        for (int t = 0; t < 8; t++) {
            float l = slo[2 * khl + t][c];
            float h = shi[2 * khl + t][c];
            va = fmaf(l, CLO[t], va);
            vh = fmaf(l, CHI[t], vh);
            vv = fmaf(h, CLO[t], vv);
            vd = fmaf(h, CHI[t], vd);
        }
        if (kh < Hc && kw < Wc) {
            size_t o = ((size_t)nc * Hc + kh) * Wc + kw;
            aa[o] = va; da[o] = vh; ad[o] = vv; dd[o] = vd;
            m_h = fmaxf(m_h, fabsf(vh));
            m_v = fmaxf(m_v, fabsf(vv));
            m_d = fmaxf(m_d, fabsf(vd));
        }
    }

#pragma unroll
    for (int o = 16; o > 0; o >>= 1) {
        m_h = fmaxf(m_h, __shfl_xor_sync(0xffffffffu, m_h, o));
        m_v = fmaxf(m_v, __shfl_xor_sync(0xffffffffu, m_v, o));
        m_d = fmaxf(m_d, __shfl_xor_sync(0xffffffffu, m_d, o));
    }
    __shared__ float rmax[8][3];
    int wid = tid >> 5, lane = tid & 31;
    if (lane == 0) { rmax[wid][0] = m_h; rmax[wid][1] = m_v; rmax[wid][2] = m_d; }
    __syncthreads();
    if (tid < 3) {
        float m = rmax[0][tid];
#pragma unroll
        for (int i = 1; i < 8; i++) m = fmaxf(m, rmax[i][tid]);
        atomicMax((int*)&g_max[(BB + tid) * NC + nc], __float_as_int(m));
    }
}

// ---------------- fused 2-D synthesis -----------------------------------
// Phase 0: stage coefficient tiles in smem, soft-threshold fused on load
// Phase 1: column IDWT smem -> smem
// Phase 2: row IDWT, 2 output pixels/thread, float2 stores
template<int Hc, int Wc, int H, int W, int BB>
__global__ void fused_idwt2(const float* __restrict__ A,  const float* __restrict__ Dh,
                            const float* __restrict__ Dv, const float* __restrict__ Dd,
                            float* __restrict__ out) {
    constexpr int TM = 32, TW = 64;
    constexpr int QR = TM / 2 + 4;  // 20 coefficient rows
    constexpr int QC = TW / 2 + 4;  // 36 coefficient cols
    __shared__ float sA[QR][QC], sH[QR][QC], sV[QR][QC], sD[QR][QC];
    __shared__ float slo[TM][QC], shi[TM][QC];

    const int w0 = blockIdx.x * TW;
    const int m0 = blockIdx.y * TM;
    const int nc = blockIdx.z;
    const int tid = threadIdx.x;
    const float th = 0.3f * g_max[(BB + 0) * NC + nc];
    const float tv = 0.3f * g_max[(BB + 1) * NC + nc];
    const float td = 0.3f * g_max[(BB + 2) * NC + nc];
    const size_t cb = (size_t)nc * Hc * Wc;
    const int q0b = m0 >> 1;
    const int c0  = w0 >> 1;

    // Phase 0: stage coefficient tiles (clamped indices; clamped values unused).
    for (int idx = tid; idx < QR * QC; idx += 256) {
        int qq = idx / QC, j = idx % QC;
        int q  = min(q0b + qq, Hc - 1);
        int wc = min(c0 + j,  Wc - 1);
        size_t o = cb + (size_t)q * Wc + wc;
        sA[qq][j] = A[o];
        sH[qq][j] = soft(Dh[o], th);
        sV[qq][j] = soft(Dv[o], tv);
        sD[qq][j] = soft(Dd[o], td);
    }
    __syncthreads();

    // Phase 1: column IDWT from smem.  local q row = (ml>>1)+i, max 18 < 20.
    for (int idx = tid; idx < TM * QC; idx += 256) {
        int ml = idx / QC, j = idx % QC;
        int fb = (ml & 1) ? 7 : 6;
        int qq = ml >> 1;
        float lo = 0.f, hi = 0.f;
#pragma unroll
        for (int i = 0; i < 4; i++) {
            int f = fb - 2 * i;
            lo = fmaf(sA[qq + i][j], CLO[f], fmaf(sH[qq + i][j], CHI[f], lo));
            hi = fmaf(sV[qq + i][j], CLO[f], fmaf(sD[qq + i][j], CHI[f], hi));
        }
        slo[ml][j] = lo;
        shi[ml][j] = hi;
    }
    __syncthreads();

    // Phase 2: row IDWT, even/odd output pair per thread, vectorized store.
    const size_t ob = (size_t)nc * H * W;
    for (int idx = tid; idx < TM * (TW / 2); idx += 256) {
        int ml = idx / (TW / 2), jp = idx % (TW / 2);
        int m = m0 + ml, w = w0 + 2 * jp;
        if (m < H && w < W) {   // W even, w even -> w and w+1 valid together
            float ae = 0.f, ao = 0.f;
#pragma unroll
            for (int i = 0; i < 4; i++) {
                float l = slo[ml][jp + i];
                float h = shi[ml][jp + i];
                ae = fmaf(l, CLO[6 - 2 * i], fmaf(h, CHI[6 - 2 * i], ae));
                ao = fmaf(l, CLO[7 - 2 * i], fmaf(h, CHI[7 - 2 * i], ao));
            }
            *reinterpret_cast<float2*>(&out[ob + (size_t)m * W + w]) =
                make_float2(ae, ao);
        }
    }
}

// ---------------- host ----------------
static inline unsigned cdiv(unsigned a, unsigned b) { return (a + b - 1) / b; }

extern "C" void kernel_launch(void* const* d_in, const int* in_sizes, int n_in,
                              void* d_out, int out_size) {
    (void)in_sizes; (void)n_in; (void)out_size;
    const float* x = (const float*)d_in[0];
    float* out = (float*)d_out;

    float *a1, *h1, *v1, *d1, *a2, *h2, *v2, *d2;
    cudaGetSymbolAddress((void**)&a1, g_a1);
    cudaGetSymbolAddress((void**)&h1, g_h1);
    cudaGetSymbolAddress((void**)&v1, g_v1);
    cudaGetSymbolAddress((void**)&d1, g_d1);
    cudaGetSymbolAddress((void**)&a2, g_a2);
    cudaGetSymbolAddress((void**)&h2, g_h2);
    cudaGetSymbolAddress((void**)&v2, g_v2);
    cudaGetSymbolAddress((void**)&d2, g_d2);

    init_max<<<3, 256>>>();

    // Level-1 analysis: x -> a1,h1,v1,d1  (+ absmax bands 0..2)
    fused_dwt2<S0, S0, S1, S1, 0><<<dim3(cdiv(S1, 32), cdiv(S1, 16), NC), 256>>>(
        x, a1, h1, v1, d1);

    // Level-2 analysis: a1 -> a2,h2,v2,d2 (+ absmax bands 3..5)
    fused_dwt2<S1, S1, S2, S2, 3><<<dim3(cdiv(S2, 32), cdiv(S2, 16), NC), 256>>>(
        a1, a2, h2, v2, d2);

    // Level-2 synthesis: (a2, h2s, v2s, d2s) -> a1r (overwrites a1)
    fused_idwt2<S2, S2, S1, S1, 3><<<dim3(cdiv(S1, 64), cdiv(S1, 32), NC), 256>>>(
        a2, h2, v2, d2, a1);

    // Level-1 synthesis: (a1r, h1s, v1s, d1s) -> out
    fused_idwt2<S1, S1, S0, S0, 0><<<dim3(cdiv(S0, 64), cdiv(S0, 32), NC), 256>>>(
        a1, h1, v1, d1, out);
}

// round 5
// speedup vs baseline: 4.4596x; 1.7002x over previous
#include <cuda_runtime.h>
#include <cuda_bf16.h>

// ---------------- problem constants ----------------
#define NC 96          // B*C = 32*3
#define S0 510
#define S1 258         // (510+7)/2
#define S2 132         // (258+7)/2

// ---------------- static scratch ----------------
__device__ float g_a1[NC * S1 * S1];   // a1, later overwritten by a1r
__device__ float g_h1[NC * S1 * S1];
__device__ float g_v1[NC * S1 * S1];
__device__ float g_d1[NC * S1 * S1];
__device__ float g_a2[NC * S2 * S2];
__device__ float g_h2[NC * S2 * S2];
__device__ float g_v2[NC * S2 * S2];
__device__ float g_d2[NC * S2 * S2];
__device__ float g_max[6 * NC];        // bands: 0..2 = h1,v1,d1 ; 3..5 = h2,v2,d2

// db4 filters (verified round 1: analysis correlation at x[2k-6] uses these directly)
__constant__ float CLO[8] = {
     0.23037781330885523f,  0.7148465705525415f,   0.6308807679295904f,
    -0.02798376941698385f, -0.18703481171888114f,  0.030841381835986965f,
     0.032883011666982945f,-0.010597401784997278f };
__constant__ float CHI[8] = {
    -0.010597401784997278f,-0.032883011666982945f, 0.030841381835986965f,
     0.18703481171888114f, -0.02798376941698385f, -0.6308807679295904f,
     0.7148465705525415f,  -0.23037781330885523f };

__device__ __forceinline__ int reflect(int idx, int S) {
    if (idx < 0)  return -1 - idx;
    if (idx >= S) return 2 * S - 1 - idx;
    return idx;
}

__device__ __forceinline__ float soft(float x, float t) {
    return copysignf(fmaxf(fabsf(x) * 1.5f - t, 0.f), x);
}

__global__ void init_max() {
    int i = blockIdx.x * blockDim.x + threadIdx.x;
    if (i < 6 * NC) g_max[i] = 0.f;
}

// ================= analysis: full-width strip, column DWT in registers =====
// Column-first order (commutes with the reference's row-first order).
// BAND MAPPING (the round-4 bug): with sclo=colLO(x), schi=colHI(x):
//   aa = rowLO(sclo)           h1 = colHI(rowLO(x)) = rowLO(schi)  -> vv
//   v1 = colLO(rowHI(x)) = rowHI(sclo)  -> vh        dd = rowHI(schi)
template<int H, int W, int Hc, int Wc, int BB>
__global__ void dwt2_strip(const float* __restrict__ x,
                           float* __restrict__ aa, float* __restrict__ da,
                           float* __restrict__ ad, float* __restrict__ dd) {
    constexpr int TKH = 8;
    constexpr int RN  = 2 * TKH + 6;   // 22 input rows per strip
    constexpr int WPAD = W + 12;       // 6 halo each side (even: 522 / 270)
    __shared__ __align__(16) float sclo[TKH][WPAD];
    __shared__ __align__(16) float schi[TKH][WPAD];

    const int kh0 = blockIdx.x * TKH;
    const int nc  = blockIdx.y;
    const int tid = threadIdx.x;
    const float* xp = x + (size_t)nc * H * W;

    // Phase A: column DWT, one input column per thread.
    for (int c = tid; c < W; c += 256) {
        float xv[RN];
        const int r0 = 2 * kh0 - 6;
#pragma unroll
        for (int rr = 0; rr < RN; rr++) {
            int r = reflect(r0 + rr, H);
            xv[rr] = xp[(size_t)r * W + c];
        }
#pragma unroll
        for (int khl = 0; khl < TKH; khl++) {
            float al = 0.f, ah = 0.f;
#pragma unroll
            for (int t = 0; t < 8; t++) {
                float v = xv[2 * khl + t];
                al = fmaf(v, CLO[t], al);
                ah = fmaf(v, CHI[t], ah);
            }
            sclo[khl][6 + c] = al;
            schi[khl][6 + c] = ah;
        }
    }
    __syncthreads();

    // Halo fill: cols -6..-1 and W..W+5 copy reflected interior columns
    // (horizontal reflection commutes with the column transform).
    if (tid < 12 * TKH) {
        int hc = tid % 12, khl = tid / 12;
        int c   = (hc < 6) ? hc - 6 : W + (hc - 6);
        int src = (c < 0) ? -1 - c : 2 * W - 1 - c;
        sclo[khl][6 + c] = sclo[khl][6 + src];
        schi[khl][6 + c] = schi[khl][6 + src];
    }
    __syncthreads();

    // Phase B: row DWT; warp w handles coefficient row kh0+w.
    const int wid = tid >> 5, lane = tid & 31;
    const int kh  = kh0 + wid;
    float m_h = 0.f, m_v = 0.f, m_d = 0.f;
    if (kh < Hc) {
        const float2* plo = (const float2*)(&sclo[wid][0]);
        const float2* phi = (const float2*)(&schi[wid][0]);
        const size_t ob = ((size_t)nc * Hc + kh) * Wc;
        for (int k = lane; k < Wc; k += 32) {
            // window floats [2k .. 2k+7] (halo offset 6 already folded in)
            float2 l0 = plo[k],     l1 = plo[k + 1];
            float2 l2 = plo[k + 2], l3 = plo[k + 3];
            float2 h0 = phi[k],     h1 = phi[k + 1];
            float2 h2 = phi[k + 2], h3 = phi[k + 3];
            float va, vh, vv, vd;
            va = fmaf(l0.x, CLO[0], fmaf(l0.y, CLO[1], fmaf(l1.x, CLO[2], fmaf(l1.y, CLO[3],
                 fmaf(l2.x, CLO[4], fmaf(l2.y, CLO[5], fmaf(l3.x, CLO[6], l3.y * CLO[7])))))));
            vh = fmaf(l0.x, CHI[0], fmaf(l0.y, CHI[1], fmaf(l1.x, CHI[2], fmaf(l1.y, CHI[3],
                 fmaf(l2.x, CHI[4], fmaf(l2.y, CHI[5], fmaf(l3.x, CHI[6], l3.y * CHI[7])))))));
            vv = fmaf(h0.x, CLO[0], fmaf(h0.y, CLO[1], fmaf(h1.x, CLO[2], fmaf(h1.y, CLO[3],
                 fmaf(h2.x, CLO[4], fmaf(h2.y, CLO[5], fmaf(h3.x, CLO[6], h3.y * CLO[7])))))));
            vd = fmaf(h0.x, CHI[0], fmaf(h0.y, CHI[1], fmaf(h1.x, CHI[2], fmaf(h1.y, CHI[3],
                 fmaf(h2.x, CHI[4], fmaf(h2.y, CHI[5], fmaf(h3.x, CHI[6], h3.y * CHI[7])))))));
            // FIXED band mapping: da (h1) <- vv = rowLO(colHI); ad (v1) <- vh = rowHI(colLO)
            aa[ob + k] = va; da[ob + k] = vv; ad[ob + k] = vh; dd[ob + k] = vd;
            m_h = fmaxf(m_h, fabsf(vv));
            m_v = fmaxf(m_v, fabsf(vh));
            m_d = fmaxf(m_d, fabsf(vd));
        }
    }

#pragma unroll
    for (int o = 16; o > 0; o >>= 1) {
        m_h = fmaxf(m_h, __shfl_xor_sync(0xffffffffu, m_h, o));
        m_v = fmaxf(m_v, __shfl_xor_sync(0xffffffffu, m_v, o));
        m_d = fmaxf(m_d, __shfl_xor_sync(0xffffffffu, m_d, o));
    }
    __shared__ float rmax[8][3];
    if (lane == 0) { rmax[wid][0] = m_h; rmax[wid][1] = m_v; rmax[wid][2] = m_d; }
    __syncthreads();
    if (tid < 3) {
        float m = rmax[0][tid];
#pragma unroll
        for (int i = 1; i < 8; i++) m = fmaxf(m, rmax[i][tid]);
        atomicMax((int*)&g_max[(BB + tid) * NC + nc], __float_as_int(m));
    }
}

// ================= synthesis: full-width strip, column IDWT in registers ===
// Block: 288 threads (Wc <= 288 for both levels -> one column per thread).
// Phase A: thread-per-coefficient-column, 4-deep register window per band with
//          soft-threshold fused on load -> column IDWT -> smem.
// Phase B: row IDWT; even/odd output pair per thread, float2 store.
template<int Hc, int Wc, int H, int W, int BB>
__global__ void idwt2_strip(const float* __restrict__ A,  const float* __restrict__ Dh,
                            const float* __restrict__ Dv, const float* __restrict__ Dd,
                            float* __restrict__ out) {
    constexpr int TM = 16;             // output rows per strip
    __shared__ __align__(16) float slo[TM][Wc];
    __shared__ __align__(16) float shi[TM][Wc];

    const int m0  = blockIdx.x * TM;
    const int nc  = blockIdx.y;
    const int tid = threadIdx.x;
    const float th = 0.3f * g_max[(BB + 0) * NC + nc];
    const float tv = 0.3f * g_max[(BB + 1) * NC + nc];
    const float td = 0.3f * g_max[(BB + 2) * NC + nc];
    const size_t cb = (size_t)nc * Hc * Wc;
    const int q0b = m0 >> 1;

    // Phase A: column IDWT (soft-enhance fused) with sliding register window.
    if (tid < Wc) {
        const int wc = tid;
        float Aw[4], Hw[4], Vw[4], Dw[4];
#pragma unroll
        for (int i = 0; i < 4; i++) {
            int q = min(q0b + i, Hc - 1);          // clamped rows feed only masked outputs
            size_t o = cb + (size_t)q * Wc + wc;
            Aw[i] = A[o];
            Hw[i] = soft(Dh[o], th);
            Vw[i] = soft(Dv[o], tv);
            Dw[i] = soft(Dd[o], td);
        }
        for (int p = 0; p < TM / 2; p++) {
            float e_lo = 0.f, o_lo = 0.f, e_hi = 0.f, o_hi = 0.f;
#pragma unroll
            for (int i = 0; i < 4; i++) {
                e_lo = fmaf(Aw[i], CLO[6 - 2 * i], fmaf(Hw[i], CHI[6 - 2 * i], e_lo));
                o_lo = fmaf(Aw[i], CLO[7 - 2 * i], fmaf(Hw[i], CHI[7 - 2 * i], o_lo));
                e_hi = fmaf(Vw[i], CLO[6 - 2 * i], fmaf(Dw[i], CHI[6 - 2 * i], e_hi));
                o_hi = fmaf(Vw[i], CLO[7 - 2 * i], fmaf(Dw[i], CHI[7 - 2 * i], o_hi));
            }
            slo[2 * p][wc]     = e_lo;
            slo[2 * p + 1][wc] = o_lo;
            shi[2 * p][wc]     = e_hi;
            shi[2 * p + 1][wc] = o_hi;
            if (p < TM / 2 - 1) {
#pragma unroll
                for (int i = 0; i < 3; i++) {
                    Aw[i] = Aw[i + 1]; Hw[i] = Hw[i + 1];
                    Vw[i] = Vw[i + 1]; Dw[i] = Dw[i + 1];
                }
                int q = min(q0b + p + 4, Hc - 1);
                size_t o = cb + (size_t)q * Wc + wc;
                Aw[3] = A[o];
                Hw[3] = soft(Dh[o], th);
                Vw[3] = soft(Dv[o], tv);
                Dw[3] = soft(Dd[o], td);
            }
        }
    }
    __syncthreads();

    // Phase B: row IDWT; 9 warps cover TM rows, lane covers output pairs.
    const int wid = tid >> 5, lane = tid & 31;
    const size_t ob = (size_t)nc * H * W;
    constexpr int NP = W / 2;   // 255 / 129 output pairs per row
    for (int rr = wid; rr < TM; rr += 9) {
        int m = m0 + rr;
        if (m >= H) break;
        float* orow = out + ob + (size_t)m * W;
        for (int wp = lane; wp < NP; wp += 32) {
            float ae = 0.f, ao = 0.f;
#pragma unroll
            for (int i = 0; i < 4; i++) {
                float l = slo[rr][wp + i];
                float h = shi[rr][wp + i];
                ae = fmaf(l, CLO[6 - 2 * i], fmaf(h, CHI[6 - 2 * i], ae));
                ao = fmaf(l, CLO[7 - 2 * i], fmaf(h, CHI[7 - 2 * i], ao));
            }
            *reinterpret_cast<float2*>(&orow[2 * wp]) = make_float2(ae, ao);
        }
    }
}

// ---------------- host ----------------
static inline unsigned cdiv(unsigned a, unsigned b) { return (a + b - 1) / b; }

extern "C" void kernel_launch(void* const* d_in, const int* in_sizes, int n_in,
                              void* d_out, int out_size) {
    (void)in_sizes; (void)n_in; (void)out_size;
    const float* x = (const float*)d_in[0];
    float* out = (float*)d_out;

    float *a1, *h1, *v1, *d1, *a2, *h2, *v2, *d2;
    cudaGetSymbolAddress((void**)&a1, g_a1);
    cudaGetSymbolAddress((void**)&h1, g_h1);
    cudaGetSymbolAddress((void**)&v1, g_v1);
    cudaGetSymbolAddress((void**)&d1, g_d1);
    cudaGetSymbolAddress((void**)&a2, g_a2);
    cudaGetSymbolAddress((void**)&h2, g_h2);
    cudaGetSymbolAddress((void**)&v2, g_v2);
    cudaGetSymbolAddress((void**)&d2, g_d2);

    init_max<<<3, 256>>>();

    // Level-1 analysis: x -> a1,h1,v1,d1 (+ absmax bands 0..2)
    dwt2_strip<S0, S0, S1, S1, 0><<<dim3(cdiv(S1, 8), NC), 256>>>(x, a1, h1, v1, d1);

    // Level-2 analysis: a1 -> a2,h2,v2,d2 (+ absmax bands 3..5)
    dwt2_strip<S1, S1, S2, S2, 3><<<dim3(cdiv(S2, 8), NC), 256>>>(a1, a2, h2, v2, d2);

    // Level-2 synthesis: (a2, h2s, v2s, d2s) -> a1r (overwrites a1)
    idwt2_strip<S2, S2, S1, S1, 3><<<dim3(cdiv(S1, 16), NC), 288>>>(a2, h2, v2, d2, a1);

    // Level-1 synthesis: (a1r, h1s, v1s, d1s) -> out
    idwt2_strip<S1, S1, S0, S0, 0><<<dim3(cdiv(S0, 16), NC), 288>>>(a1, h1, v1, d1, out);
}

// round 6
// speedup vs baseline: 5.0273x; 1.1273x over previous
#include <cuda_runtime.h>
#include <cuda_bf16.h>

// ---------------- problem constants ----------------
#define NC 96          // B*C = 32*3
#define S0 510
#define S1 258         // (510+7)/2
#define S2 132         // (258+7)/2

// ---------------- static scratch ----------------
__device__ float g_a1[NC * S1 * S1];   // a1, later overwritten by a1r
__device__ float g_h1[NC * S1 * S1];
__device__ float g_v1[NC * S1 * S1];
__device__ float g_d1[NC * S1 * S1];
__device__ float g_a2[NC * S2 * S2];
__device__ float g_h2[NC * S2 * S2];
__device__ float g_v2[NC * S2 * S2];
__device__ float g_d2[NC * S2 * S2];
__device__ float g_max[6 * NC];        // bands: 0..2 = h1,v1,d1 ; 3..5 = h2,v2,d2

// db4 filters (verified round 1)
__constant__ float CLO[8] = {
     0.23037781330885523f,  0.7148465705525415f,   0.6308807679295904f,
    -0.02798376941698385f, -0.18703481171888114f,  0.030841381835986965f,
     0.032883011666982945f,-0.010597401784997278f };
__constant__ float CHI[8] = {
    -0.010597401784997278f,-0.032883011666982945f, 0.030841381835986965f,
     0.18703481171888114f, -0.02798376941698385f, -0.6308807679295904f,
     0.7148465705525415f,  -0.23037781330885523f };

__device__ __forceinline__ int reflect(int idx, int S) {
    if (idx < 0)  return -1 - idx;
    if (idx >= S) return 2 * S - 1 - idx;
    return idx;
}

__device__ __forceinline__ float soft(float x, float t) {
    return copysignf(fmaxf(fabsf(x) * 1.5f - t, 0.f), x);
}

__global__ void init_max() {
    int i = blockIdx.x * blockDim.x + threadIdx.x;
    if (i < 6 * NC) g_max[i] = 0.f;
}

// ================= analysis: full-width strip, column DWT in registers =====
// Band mapping (fixed in round 5): da(h1) <- rowLO(colHI)=vv ; ad(v1) <- rowHI(colLO)=vh.
template<int H, int W, int Hc, int Wc, int BB, int BLK>
__global__ void __launch_bounds__(BLK) dwt2_strip(
        const float* __restrict__ x,
        float* __restrict__ aa, float* __restrict__ da,
        float* __restrict__ ad, float* __restrict__ dd) {
    constexpr int TKH = 8;
    constexpr int RN  = 2 * TKH + 6;   // 22 input rows per strip
    constexpr int WPAD = W + 12;       // 6 halo each side
    constexpr int NW  = BLK / 32;
    constexpr int WPR = (NW >= TKH) ? NW / TKH : 1;   // warps per coeff row
    __shared__ __align__(16) float sclo[TKH][WPAD];
    __shared__ __align__(16) float schi[TKH][WPAD];

    const int kh0 = blockIdx.x * TKH;
    const int nc  = blockIdx.y;
    const int tid = threadIdx.x;
    const float* xp = x + (size_t)nc * H * W;

    // Phase A: column DWT, one input column per thread (single pass: BLK >= W).
    for (int c = tid; c < W; c += BLK) {
        float xv[RN];
        const int r0 = 2 * kh0 - 6;
#pragma unroll
        for (int rr = 0; rr < RN; rr++) {
            int r = reflect(r0 + rr, H);
            xv[rr] = xp[(size_t)r * W + c];
        }
#pragma unroll
        for (int khl = 0; khl < TKH; khl++) {
            float al = 0.f, ah = 0.f;
#pragma unroll
            for (int t = 0; t < 8; t++) {
                float v = xv[2 * khl + t];
                al = fmaf(v, CLO[t], al);
                ah = fmaf(v, CHI[t], ah);
            }
            sclo[khl][6 + c] = al;
            schi[khl][6 + c] = ah;
        }
    }
    __syncthreads();

    // Halo fill: horizontal reflection commutes with the column transform.
    if (tid < 12 * TKH) {
        int hc = tid % 12, khl = tid / 12;
        int c   = (hc < 6) ? hc - 6 : W + (hc - 6);
        int src = (c < 0) ? -1 - c : 2 * W - 1 - c;
        sclo[khl][6 + c] = sclo[khl][6 + src];
        schi[khl][6 + c] = schi[khl][6 + src];
    }
    __syncthreads();

    // Phase B: row DWT; WPR warps cooperate on each coefficient row.
    const int wid = tid >> 5, lane = tid & 31;
    const int row = wid / WPR, sub = wid % WPR;
    float m_h = 0.f, m_v = 0.f, m_d = 0.f;
    if (row < TKH) {
        const int kh = kh0 + row;
        if (kh < Hc) {
            const float2* plo = (const float2*)(&sclo[row][0]);
            const float2* phi = (const float2*)(&schi[row][0]);
            const size_t ob = ((size_t)nc * Hc + kh) * Wc;
            for (int k = lane + 32 * sub; k < Wc; k += 32 * WPR) {
                float2 l0 = plo[k],     l1 = plo[k + 1];
                float2 l2 = plo[k + 2], l3 = plo[k + 3];
                float2 h0 = phi[k],     h1 = phi[k + 1];
                float2 h2 = phi[k + 2], h3 = phi[k + 3];
                float va, vh, vv, vd;
                va = fmaf(l0.x, CLO[0], fmaf(l0.y, CLO[1], fmaf(l1.x, CLO[2], fmaf(l1.y, CLO[3],
                     fmaf(l2.x, CLO[4], fmaf(l2.y, CLO[5], fmaf(l3.x, CLO[6], l3.y * CLO[7])))))));
                vh = fmaf(l0.x, CHI[0], fmaf(l0.y, CHI[1], fmaf(l1.x, CHI[2], fmaf(l1.y, CHI[3],
                     fmaf(l2.x, CHI[4], fmaf(l2.y, CHI[5], fmaf(l3.x, CHI[6], l3.y * CHI[7])))))));
                vv = fmaf(h0.x, CLO[0], fmaf(h0.y, CLO[1], fmaf(h1.x, CLO[2], fmaf(h1.y, CLO[3],
                     fmaf(h2.x, CLO[4], fmaf(h2.y, CLO[5], fmaf(h3.x, CLO[6], h3.y * CLO[7])))))));
                vd = fmaf(h0.x, CHI[0], fmaf(h0.y, CHI[1], fmaf(h1.x, CHI[2], fmaf(h1.y, CHI[3],
                     fmaf(h2.x, CHI[4], fmaf(h2.y, CHI[5], fmaf(h3.x, CHI[6], h3.y * CHI[7])))))));
                aa[ob + k] = va; da[ob + k] = vv; ad[ob + k] = vh; dd[ob + k] = vd;
                m_h = fmaxf(m_h, fabsf(vv));
                m_v = fmaxf(m_v, fabsf(vh));
                m_d = fmaxf(m_d, fabsf(vd));
            }
        }
    }

#pragma unroll
    for (int o = 16; o > 0; o >>= 1) {
        m_h = fmaxf(m_h, __shfl_xor_sync(0xffffffffu, m_h, o));
        m_v = fmaxf(m_v, __shfl_xor_sync(0xffffffffu, m_v, o));
        m_d = fmaxf(m_d, __shfl_xor_sync(0xffffffffu, m_d, o));
    }
    __shared__ float rmax[NW][3];
    if (lane == 0) { rmax[wid][0] = m_h; rmax[wid][1] = m_v; rmax[wid][2] = m_d; }
    __syncthreads();
    if (tid < 3) {
        float m = rmax[0][tid];
#pragma unroll
        for (int i = 1; i < NW; i++) m = fmaxf(m, rmax[i][tid]);
        atomicMax((int*)&g_max[(BB + tid) * NC + nc], __float_as_int(m));
    }
}

// ================= synthesis: full-width strip, column IDWT in registers ===
// Phase A: thread-per-coefficient-column; FULL 11-row window per band preloaded
//          upfront (44 independent loads -> high MLP), soft-threshold fused.
// Phase B: row IDWT; even/odd output pair per thread, float2 store.
template<int Hc, int Wc, int H, int W, int BB, int BLK>
__global__ void __launch_bounds__(BLK) idwt2_strip(
        const float* __restrict__ A,  const float* __restrict__ Dh,
        const float* __restrict__ Dv, const float* __restrict__ Dd,
        float* __restrict__ out) {
    constexpr int TM = 16;             // output rows per strip
    constexpr int RW = TM / 2 + 3;     // 11 coefficient rows cover the strip
    constexpr int NW = BLK / 32;
    __shared__ __align__(16) float slo[TM][Wc];
    __shared__ __align__(16) float shi[TM][Wc];

    const int m0  = blockIdx.x * TM;
    const int nc  = blockIdx.y;
    const int tid = threadIdx.x;
    const float th = 0.3f * g_max[(BB + 0) * NC + nc];
    const float tv = 0.3f * g_max[(BB + 1) * NC + nc];
    const float td = 0.3f * g_max[(BB + 2) * NC + nc];
    const size_t cb = (size_t)nc * Hc * Wc;
    const int q0b = m0 >> 1;

    // Phase A: column IDWT (soft-enhance fused), full register window.
    if (tid < Wc) {
        const int wc = tid;
        float Aw[RW], Hw[RW], Vw[RW], Dw[RW];
#pragma unroll
        for (int i = 0; i < RW; i++) {
            int q = min(q0b + i, Hc - 1);   // clamped rows feed only masked outputs
            size_t o = cb + (size_t)q * Wc + wc;
            Aw[i] = A[o];
            Hw[i] = soft(Dh[o], th);
            Vw[i] = soft(Dv[o], tv);
            Dw[i] = soft(Dd[o], td);
        }
#pragma unroll
        for (int p = 0; p < TM / 2; p++) {
            float e_lo = 0.f, o_lo = 0.f, e_hi = 0.f, o_hi = 0.f;
#pragma unroll
            for (int i = 0; i < 4; i++) {
                e_lo = fmaf(Aw[p + i], CLO[6 - 2 * i], fmaf(Hw[p + i], CHI[6 - 2 * i], e_lo));
                o_lo = fmaf(Aw[p + i], CLO[7 - 2 * i], fmaf(Hw[p + i], CHI[7 - 2 * i], o_lo));
                e_hi = fmaf(Vw[p + i], CLO[6 - 2 * i], fmaf(Dw[p + i], CHI[6 - 2 * i], e_hi));
                o_hi = fmaf(Vw[p + i], CLO[7 - 2 * i], fmaf(Dw[p + i], CHI[7 - 2 * i], o_hi));
            }
            slo[2 * p][wc]     = e_lo;
            slo[2 * p + 1][wc] = o_lo;
            shi[2 * p][wc]     = e_hi;
            shi[2 * p + 1][wc] = o_hi;
        }
    }
    __syncthreads();

    // Phase B: row IDWT; NW warps cover TM rows, lane covers output pairs.
    const int wid = tid >> 5, lane = tid & 31;
    const size_t ob = (size_t)nc * H * W;
    constexpr int NP = W / 2;   // output pairs per row
    for (int rr = wid; rr < TM; rr += NW) {
        int m = m0 + rr;
        if (m >= H) break;
        float* orow = out + ob + (size_t)m * W;
        for (int wp = lane; wp < NP; wp += 32) {
            float ae = 0.f, ao = 0.f;
#pragma unroll
            for (int i = 0; i < 4; i++) {
                float l = slo[rr][wp + i];
                float h = shi[rr][wp + i];
                ae = fmaf(l, CLO[6 - 2 * i], fmaf(h, CHI[6 - 2 * i], ae));
                ao = fmaf(l, CLO[7 - 2 * i], fmaf(h, CHI[7 - 2 * i], ao));
            }
            *reinterpret_cast<float2*>(&orow[2 * wp]) = make_float2(ae, ao);
        }
    }
}

// ---------------- host ----------------
static inline unsigned cdiv(unsigned a, unsigned b) { return (a + b - 1) / b; }

extern "C" void kernel_launch(void* const* d_in, const int* in_sizes, int n_in,
                              void* d_out, int out_size) {
    (void)in_sizes; (void)n_in; (void)out_size;
    const float* x = (const float*)d_in[0];
    float* out = (float*)d_out;

    float *a1, *h1, *v1, *d1, *a2, *h2, *v2, *d2;
    cudaGetSymbolAddress((void**)&a1, g_a1);
    cudaGetSymbolAddress((void**)&h1, g_h1);
    cudaGetSymbolAddress((void**)&v1, g_v1);
    cudaGetSymbolAddress((void**)&d1, g_d1);
    cudaGetSymbolAddress((void**)&a2, g_a2);
    cudaGetSymbolAddress((void**)&h2, g_h2);
    cudaGetSymbolAddress((void**)&v2, g_v2);
    cudaGetSymbolAddress((void**)&d2, g_d2);

    init_max<<<3, 256>>>();

    // Level-1 analysis: x -> a1,h1,v1,d1 (+ absmax bands 0..2); 512 thr: W=510 one pass
    dwt2_strip<S0, S0, S1, S1, 0, 512><<<dim3(cdiv(S1, 8), NC), 512>>>(x, a1, h1, v1, d1);

    // Level-2 analysis: a1 -> a2,h2,v2,d2 (+ absmax bands 3..5); 288 thr: W=258 one pass
    dwt2_strip<S1, S1, S2, S2, 3, 288><<<dim3(cdiv(S2, 8), NC), 288>>>(a1, a2, h2, v2, d2);

    // Level-2 synthesis: (a2, h2s, v2s, d2s) -> a1r (overwrites a1); 160 thr (Wc=132)
    idwt2_strip<S2, S2, S1, S1, 3, 160><<<dim3(cdiv(S1, 16), NC), 160>>>(a2, h2, v2, d2, a1);

    // Level-1 synthesis: (a1r, h1s, v1s, d1s) -> out; 288 thr (Wc=258)
    idwt2_strip<S1, S1, S0, S0, 0, 288><<<dim3(cdiv(S0, 16), NC), 288>>>(a1, h1, v1, d1, out);
}

// round 7
// speedup vs baseline: 5.1874x; 1.0319x over previous
#include <cuda_runtime.h>
#include <cuda_bf16.h>

// ---------------- problem constants ----------------
#define NC 96          // B*C = 32*3
#define S0 510
#define S1 258         // (510+7)/2
#define S2 132         // (258+7)/2

// ---------------- static scratch ----------------
__device__ float g_a1[NC * S1 * S1];   // a1, later overwritten by a1r
__device__ float g_h1[NC * S1 * S1];
__device__ float g_v1[NC * S1 * S1];
__device__ float g_d1[NC * S1 * S1];
__device__ float g_a2[NC * S2 * S2];
__device__ float g_h2[NC * S2 * S2];
__device__ float g_v2[NC * S2 * S2];
__device__ float g_d2[NC * S2 * S2];
__device__ float g_max[6 * NC];        // bands: 0..2 = h1,v1,d1 ; 3..5 = h2,v2,d2

// db4 filters (verified round 1)
__constant__ float CLO[8] = {
     0.23037781330885523f,  0.7148465705525415f,   0.6308807679295904f,
    -0.02798376941698385f, -0.18703481171888114f,  0.030841381835986965f,
     0.032883011666982945f,-0.010597401784997278f };
__constant__ float CHI[8] = {
    -0.010597401784997278f,-0.032883011666982945f, 0.030841381835986965f,
     0.18703481171888114f, -0.02798376941698385f, -0.6308807679295904f,
     0.7148465705525415f,  -0.23037781330885523f };

__device__ __forceinline__ int reflect(int idx, int S) {
    if (idx < 0)  return -1 - idx;
    if (idx >= S) return 2 * S - 1 - idx;
    return idx;
}

__device__ __forceinline__ float soft(float x, float t) {
    return copysignf(fmaxf(fabsf(x) * 1.5f - t, 0.f), x);
}

__global__ void init_max() {
    int i = blockIdx.x * blockDim.x + threadIdx.x;
    if (i < 6 * NC) g_max[i] = 0.f;
}

// ================= analysis: full-width strip, column DWT in registers =====
// Band mapping (fixed round 5): da(h1) <- rowLO(colHI)=vv ; ad(v1) <- rowHI(colLO)=vh.
template<int H, int W, int Hc, int Wc, int BB, int BLK>
__global__ void __launch_bounds__(BLK) dwt2_strip(
        const float* __restrict__ x,
        float* __restrict__ aa, float* __restrict__ da,
        float* __restrict__ ad, float* __restrict__ dd) {
    constexpr int TKH = 8;
    constexpr int RN  = 2 * TKH + 6;   // 22 input rows per strip
    constexpr int WPAD = W + 12;       // 6 halo each side
    constexpr int NW  = BLK / 32;
    constexpr int WPR = (NW >= TKH) ? NW / TKH : 1;   // warps per coeff row
    __shared__ __align__(16) float sclo[TKH][WPAD];
    __shared__ __align__(16) float schi[TKH][WPAD];

    const int kh0 = blockIdx.x * TKH;
    const int nc  = blockIdx.y;
    const int tid = threadIdx.x;
    const float* xp = x + (size_t)nc * H * W;

    // Phase A: column DWT, one input column per thread (single pass: BLK >= W).
    for (int c = tid; c < W; c += BLK) {
        float xv[RN];
        const int r0 = 2 * kh0 - 6;
#pragma unroll
        for (int rr = 0; rr < RN; rr++) {
            int r = reflect(r0 + rr, H);
            xv[rr] = xp[(size_t)r * W + c];
        }
#pragma unroll
        for (int khl = 0; khl < TKH; khl++) {
            float al = 0.f, ah = 0.f;
#pragma unroll
            for (int t = 0; t < 8; t++) {
                float v = xv[2 * khl + t];
                al = fmaf(v, CLO[t], al);
                ah = fmaf(v, CHI[t], ah);
            }
            sclo[khl][6 + c] = al;
            schi[khl][6 + c] = ah;
        }
    }
    __syncthreads();

    // Halo fill: horizontal reflection commutes with the column transform.
    if (tid < 12 * TKH) {
        int hc = tid % 12, khl = tid / 12;
        int c   = (hc < 6) ? hc - 6 : W + (hc - 6);
        int src = (c < 0) ? -1 - c : 2 * W - 1 - c;
        sclo[khl][6 + c] = sclo[khl][6 + src];
        schi[khl][6 + c] = schi[khl][6 + src];
    }
    __syncthreads();

    // Phase B: row DWT; WPR warps cooperate on each coefficient row.
    const int wid = tid >> 5, lane = tid & 31;
    const int row = wid / WPR, sub = wid % WPR;
    float m_h = 0.f, m_v = 0.f, m_d = 0.f;
    if (row < TKH) {
        const int kh = kh0 + row;
        if (kh < Hc) {
            const float2* plo = (const float2*)(&sclo[row][0]);
            const float2* phi = (const float2*)(&schi[row][0]);
            const size_t ob = ((size_t)nc * Hc + kh) * Wc;
            for (int k = lane + 32 * sub; k < Wc; k += 32 * WPR) {
                float2 l0 = plo[k],     l1 = plo[k + 1];
                float2 l2 = plo[k + 2], l3 = plo[k + 3];
                float2 h0 = phi[k],     h1 = phi[k + 1];
                float2 h2 = phi[k + 2], h3 = phi[k + 3];
                float va, vh, vv, vd;
                va = fmaf(l0.x, CLO[0], fmaf(l0.y, CLO[1], fmaf(l1.x, CLO[2], fmaf(l1.y, CLO[3],
                     fmaf(l2.x, CLO[4], fmaf(l2.y, CLO[5], fmaf(l3.x, CLO[6], l3.y * CLO[7])))))));
                vh = fmaf(l0.x, CHI[0], fmaf(l0.y, CHI[1], fmaf(l1.x, CHI[2], fmaf(l1.y, CHI[3],
                     fmaf(l2.x, CHI[4], fmaf(l2.y, CHI[5], fmaf(l3.x, CHI[6], l3.y * CHI[7])))))));
                vv = fmaf(h0.x, CLO[0], fmaf(h0.y, CLO[1], fmaf(h1.x, CLO[2], fmaf(h1.y, CLO[3],
                     fmaf(h2.x, CLO[4], fmaf(h2.y, CLO[5], fmaf(h3.x, CLO[6], h3.y * CLO[7])))))));
                vd = fmaf(h0.x, CHI[0], fmaf(h0.y, CHI[1], fmaf(h1.x, CHI[2], fmaf(h1.y, CHI[3],
                     fmaf(h2.x, CHI[4], fmaf(h2.y, CHI[5], fmaf(h3.x, CHI[6], h3.y * CHI[7])))))));
                aa[ob + k] = va; da[ob + k] = vv; ad[ob + k] = vh; dd[ob + k] = vd;
                m_h = fmaxf(m_h, fabsf(vv));
                m_v = fmaxf(m_v, fabsf(vh));
                m_d = fmaxf(m_d, fabsf(vd));
            }
        }
    }

#pragma unroll
    for (int o = 16; o > 0; o >>= 1) {
        m_h = fmaxf(m_h, __shfl_xor_sync(0xffffffffu, m_h, o));
        m_v = fmaxf(m_v, __shfl_xor_sync(0xffffffffu, m_v, o));
        m_d = fmaxf(m_d, __shfl_xor_sync(0xffffffffu, m_d, o));
    }
    __shared__ float rmax[NW][3];
    if (lane == 0) { rmax[wid][0] = m_h; rmax[wid][1] = m_v; rmax[wid][2] = m_d; }
    __syncthreads();
    if (tid < 3) {
        float m = rmax[0][tid];
#pragma unroll
        for (int i = 1; i < NW; i++) m = fmaxf(m, rmax[i][tid]);
        atomicMax((int*)&g_max[(BB + tid) * NC + nc], __float_as_int(m));
    }
}

// ================= synthesis: full-width strip, split column IDWT ==========
// Phase A: thread = (column, half). Each half covers 4 p-values (8 output
//          rows) from a 7-row x 4-band register window (28 regs).  Raw values
//          loaded as one independent LDG batch, then soft-thresholded.
// Phase B: row IDWT; even/odd output pair per thread, float2 store.
template<int Hc, int Wc, int H, int W, int BB, int BLK>
__global__ void __launch_bounds__(BLK) idwt2_strip(
        const float* __restrict__ A,  const float* __restrict__ Dh,
        const float* __restrict__ Dv, const float* __restrict__ Dd,
        float* __restrict__ out) {
    constexpr int TM  = 16;            // output rows per strip
    constexpr int PR  = 4;             // p-values per half
    constexpr int RWH = PR + 3;        // 7 coefficient rows per half
    constexpr int NW  = BLK / 32;
    __shared__ __align__(16) float slo[TM][Wc];
    __shared__ __align__(16) float shi[TM][Wc];

    const int m0  = blockIdx.x * TM;
    const int nc  = blockIdx.y;
    const int tid = threadIdx.x;
    const float th = 0.3f * g_max[(BB + 0) * NC + nc];
    const float tv = 0.3f * g_max[(BB + 1) * NC + nc];
    const float td = 0.3f * g_max[(BB + 2) * NC + nc];
    const size_t cb = (size_t)nc * Hc * Wc;
    const int q0b = m0 >> 1;

    // Phase A: 2*Wc active threads.
    if (tid < 2 * Wc) {
        const int wc = (tid < Wc) ? tid : tid - Wc;
        const int hf = (tid < Wc) ? 0 : 1;
        const int pb = hf * PR;                 // p base: 0 or 4
        const int qs = q0b + pb;                // first coeff row of this half

        float Aw[RWH], Hw[RWH], Vw[RWH], Dw[RWH];
        // one independent load batch (28 LDGs)
#pragma unroll
        for (int i = 0; i < RWH; i++) {
            int q = min(qs + i, Hc - 1);        // clamped rows feed only masked outputs
            size_t o = cb + (size_t)q * Wc + wc;
            Aw[i] = A[o];
            Hw[i] = Dh[o];
            Vw[i] = Dv[o];
            Dw[i] = Dd[o];
        }
#pragma unroll
        for (int i = 0; i < RWH; i++) {
            Hw[i] = soft(Hw[i], th);
            Vw[i] = soft(Vw[i], tv);
            Dw[i] = soft(Dw[i], td);
        }
#pragma unroll
        for (int pp = 0; pp < PR; pp++) {
            const int ml = 2 * (pb + pp);       // strip-local even output row
            float e_lo = 0.f, o_lo = 0.f, e_hi = 0.f, o_hi = 0.f;
#pragma unroll
            for (int i = 0; i < 4; i++) {
                e_lo = fmaf(Aw[pp + i], CLO[6 - 2 * i], fmaf(Hw[pp + i], CHI[6 - 2 * i], e_lo));
                o_lo = fmaf(Aw[pp + i], CLO[7 - 2 * i], fmaf(Hw[pp + i], CHI[7 - 2 * i], o_lo));
                e_hi = fmaf(Vw[pp + i], CLO[6 - 2 * i], fmaf(Dw[pp + i], CHI[6 - 2 * i], e_hi));
                o_hi = fmaf(Vw[pp + i], CLO[7 - 2 * i], fmaf(Dw[pp + i], CHI[7 - 2 * i], o_hi));
            }
            slo[ml][wc]     = e_lo;
            slo[ml + 1][wc] = o_lo;
            shi[ml][wc]     = e_hi;
            shi[ml + 1][wc] = o_hi;
        }
    }
    __syncthreads();

    // Phase B: row IDWT; NW warps cover TM rows, lane covers output pairs.
    const int wid = tid >> 5, lane = tid & 31;
    const size_t ob = (size_t)nc * H * W;
    constexpr int NP = W / 2;   // output pairs per row
    for (int rr = wid; rr < TM; rr += NW) {
        int m = m0 + rr;
        if (m >= H) break;
        float* orow = out + ob + (size_t)m * W;
        for (int wp = lane; wp < NP; wp += 32) {
            float ae = 0.f, ao = 0.f;
#pragma unroll
            for (int i = 0; i < 4; i++) {
                float l = slo[rr][wp + i];
                float h = shi[rr][wp + i];
                ae = fmaf(l, CLO[6 - 2 * i], fmaf(h, CHI[6 - 2 * i], ae));
                ao = fmaf(l, CLO[7 - 2 * i], fmaf(h, CHI[7 - 2 * i], ao));
            }
            *reinterpret_cast<float2*>(&orow[2 * wp]) = make_float2(ae, ao);
        }
    }
}

// ---------------- host ----------------
static inline unsigned cdiv(unsigned a, unsigned b) { return (a + b - 1) / b; }

extern "C" void kernel_launch(void* const* d_in, const int* in_sizes, int n_in,
                              void* d_out, int out_size) {
    (void)in_sizes; (void)n_in; (void)out_size;
    const float* x = (const float*)d_in[0];
    float* out = (float*)d_out;

    float *a1, *h1, *v1, *d1, *a2, *h2, *v2, *d2;
    cudaGetSymbolAddress((void**)&a1, g_a1);
    cudaGetSymbolAddress((void**)&h1, g_h1);
    cudaGetSymbolAddress((void**)&v1, g_v1);
    cudaGetSymbolAddress((void**)&d1, g_d1);
    cudaGetSymbolAddress((void**)&a2, g_a2);
    cudaGetSymbolAddress((void**)&h2, g_h2);
    cudaGetSymbolAddress((void**)&v2, g_v2);
    cudaGetSymbolAddress((void**)&d2, g_d2);

    init_max<<<3, 256>>>();

    // Level-1 analysis: x -> a1,h1,v1,d1 (+ absmax bands 0..2)
    dwt2_strip<S0, S0, S1, S1, 0, 512><<<dim3(cdiv(S1, 8), NC), 512>>>(x, a1, h1, v1, d1);

    // Level-2 analysis: a1 -> a2,h2,v2,d2 (+ absmax bands 3..5)
    dwt2_strip<S1, S1, S2, S2, 3, 288><<<dim3(cdiv(S2, 8), NC), 288>>>(a1, a2, h2, v2, d2);

    // Level-2 synthesis -> a1r (overwrites a1); 2*Wc = 264 active -> 288 thr
    idwt2_strip<S2, S2, S1, S1, 3, 288><<<dim3(cdiv(S1, 16), NC), 288>>>(a2, h2, v2, d2, a1);

    // Level-1 synthesis -> out; 2*Wc = 516 active -> 544 thr
    idwt2_strip<S1, S1, S0, S0, 0, 544><<<dim3(cdiv(S0, 16), NC), 544>>>(a1, h1, v1, d1, out);
}